// round 11
// baseline (speedup 1.0000x reference)
#include <cuda_runtime.h>
#include <cstdint>

typedef unsigned long long ull;

#define SENS   1024
#define P_CNT  256
#define KPSF   64

#define SROW   305                    // sBlk row stride (odd => conflict-free)
#define SK_ULL   (34 * 34)            // [u 34][dy 34pad] float2(k1[u-1], k0[u])
#define SB_FLT   (32 * SROW + 4)      // [s][ts 34 * 9 + n], ts=0/33 are zero pads
#define SMEM_BYTES (SK_ULL * 8 + SB_FLT * 4)

#define ZERO_CTAS   8192              // 8*1024*1024 floats / 4 / 256
#define BINPSF_TOT  (P_CNT * 2 * 34 * 34)
#define BINPSF_CTAS ((BINPSF_TOT + 255) / 256)

// Paired binned PSF: [p][ry][u 34][dy 34pad] -> float2(k_rx1[u-1], k_rx0[u])
__device__ float2 g_K[P_CNT * 2 * 34 * 34];

// packed fma: acc (float2, aliased as b64) += k * b, both f32x2
#define PFMA(kv, bv, c) \
    asm("fma.rn.f32x2 %0, %1, %2, %0;" \
        : "+l"(*reinterpret_cast<ull*>(&(c))) : "l"(kv), "l"(bv))

__device__ __forceinline__ ull dup2(float v) {
    ull d;
    asm("mov.b64 %0, {%1, %1};" : "=l"(d) : "f"(v));
    return d;
}
#define RED2(ptr, a, b) \
    asm volatile("red.global.add.v2.f32 [%0], {%1, %2};" :: "l"(ptr), "f"(a), "f"(b) : "memory")
#define RED1(ptr, a) \
    asm volatile("red.global.add.f32 [%0], %1;" :: "l"(ptr), "f"(a) : "memory")

// ---------------- kernel 1: setup = zero sensor + bin PSF (merged) -----------
__global__ void setup_kernel(const float* __restrict__ psf,
                             float4* __restrict__ out) {
    const int bid = blockIdx.x;
    if (bid < ZERO_CTAS) {
        out[bid * 256 + threadIdx.x] = make_float4(0.f, 0.f, 0.f, 0.f);
        return;
    }
    int idx = (bid - ZERO_CTAS) * 256 + threadIdx.x;
    if (idx >= BINPSF_TOT) return;
    int dy = idx % 34;
    int u  = (idx / 34) % 34;
    int ry = (idx / (34 * 34)) & 1;
    int p  = idx / (34 * 34 * 2);
    float sx = 0.f, sy = 0.f;
    if (dy < 33) {
        const float* w = psf + (size_t)p * KPSF * KPSF;
        int r0  = 63 - ry - 2 * dy;
        int cx0 = 64 - 2 * u;       // rx=1, dx=u-1
        int cy0 = 63 - 2 * u;       // rx=0, dx=u
        #pragma unroll
        for (int a = 0; a < 2; ++a) {
            int rr = r0 + a;
            if (rr < 0 || rr > 63) continue;
            const float* row = w + rr * KPSF;
            #pragma unroll
            for (int c = 0; c < 2; ++c) {
                int ccx = cx0 + c;
                if (ccx >= 0 && ccx <= 63) sx += row[ccx];
                int ccy = cy0 + c;
                if (ccy >= 0 && ccy <= 63) sy += row[ccy];
            }
        }
    }
    g_K[idx] = make_float2(sx, sy);
}

// ---------------- kernel 2: conv, mixed FFMA2/FFMA stream --------------------
// RF banks cap fma.f32x2 at 1 per 3 cyc (3 distinct 64-bit src operands).
// Scalar FFMA is rt=2 and fits in the gaps: route 11 of 33 dy-taps through
// scalar fmaf on the acc halves (1:1 instruction mix) -> 1.5x MAC throughput.
__global__ __launch_bounds__(128, 3)
void conv_splat_kernel(const float* __restrict__ imgs,
                       const float* __restrict__ xc,
                       const float* __restrict__ yc,
                       float* __restrict__ out)
{
    extern __shared__ ull dynsmem[];
    ull*   sK   = dynsmem;                                  // [34][34] float2
    float* sBlk = reinterpret_cast<float*>(dynsmem + SK_ULL); // [s][ts*9+n], stride 305

    const int bid  = blockIdx.x;
    // heavy-first octet ordering: groups of 512 CTAs, descending u-trip work
    const int grp  = bid >> 9;
    const int oct  = (0x70615243u >> (grp * 4)) & 7;   // {3,4,2,5,1,6,0,7}
    const int ry   = bid & 1;
    const int p    = (bid >> 1) & 255;
    const int tid  = threadIdx.x;
    const int lane = tid & 31;
    const int warp = tid >> 5;
    const int n    = lane & 7;
    const int xi   = (lane >> 3) & 1;
    const int sh   = lane >> 4;
    const int base = oct * 8 + warp * 2;
    const int qx   = base + xi;
    const int s0   = sh * 16;

    // load paired kernel (16B vectors)
    {
        const ulonglong2* kg = reinterpret_cast<const ulonglong2*>(
            reinterpret_cast<const ull*>(g_K) + (size_t)(p * 2 + ry) * SK_ULL);
        ulonglong2* sk2 = reinterpret_cast<ulonglong2*>(sK);
        for (int i = tid; i < SK_ULL / 2; i += 128) sk2[i] = kg[i];
    }
    // zero the two pad t-columns (ts = 0 and ts = 33)
    for (int i = tid; i < 32 * 2 * 8; i += 128) {
        int s  = i >> 4;
        int r  = i & 15;
        int ts = (r & 1) ? 33 : 0;
        int nn = r >> 1;
        sBlk[s * SROW + ts * 9 + nn] = 0.f;
    }
    // fill interior with float4 gmem loads (stride-9 scalar STS, conflict-free)
    const int bh = p & 15, bw = p >> 4;          // p = bw*16 + bh
    for (int i = tid; i < 32 * 8 * 8; i += 128) {
        int q  = i & 7;                           // float4 quad within row
        int nn = (i >> 3) & 7;
        int s  = i >> 6;
        float4 v = *reinterpret_cast<const float4*>(
            imgs + ((size_t)nn * 512 + bh * 32 + s) * 512 + bw * 32 + 4 * q);
        float* dst = &sBlk[s * SROW + (4 * q + 1) * 9 + nn];
        dst[0]      = v.x;
        dst[9]      = v.y;
        dst[18]     = v.z;
        dst[27]     = v.w;
    }
    __syncthreads();

    // splat geometry (all in-bounds for this problem's centers).
    const int ic = 512 + __float2int_rn(xc[p] * 1e6f);
    const int jc = 512 + __float2int_rn(yc[p] * 1e6f);
    float* oemit = out + (size_t)n * SENS * SENS
                 + (size_t)(ic - 63 + ry + 2 * s0) * SENS
                 + (jc - 64 + 2 * qx);

    // warp-uniform u range (union of useful taps over 2 qx)
    const int ulo = max(0, base - 31);
    const int uhi = min(33, base + 1);

    // per-thread b column base at (s = s0, ts = qx+1)
    const float* bcol0 = sBlk + s0 * SROW + (qx + 1) * 9 + n;

    float2 acc[40];
    #pragma unroll
    for (int i = 0; i < 40; ++i) acc[i] = make_float2(0.f, 0.f);

    #pragma unroll
    for (int i = 0; i < 16; i += 8) {               // 8 local s-steps jointly
        const float* bp = bcol0 + i * SROW - ulo * 9;
        const ull*   kc = sK + ulo * 34;
        float braw[8];
        #pragma unroll
        for (int j = 0; j < 8; ++j) braw[j] = bp[j * SROW];
        for (int u = ulo; u <= uhi; ++u) {
            ull bd[8];
            #pragma unroll
            for (int j = 0; j < 8; ++j) bd[j] = dup2(braw[j]);
            bp -= 9;
            if (u < uhi) {
                #pragma unroll
                for (int j = 0; j < 8; ++j) braw[j] = bp[j * SROW];
            }
            // mixed-tap chain: packed pairs double-buffered, scalar pairs
            // (e % 3 == 2) via fmaf on acc halves (F2:F1 = 1:1 instruction mix)
            ulonglong2 pkk = *reinterpret_cast<const ulonglong2*>(kc);
            float4     skk = *reinterpret_cast<const float4*>(kc + 4);
            #pragma unroll
            for (int e = 0; e < 16; ++e) {
                if (e % 3 == 2) {
                    float4 cur = skk;
                    if (e + 3 <= 14)
                        skk = *reinterpret_cast<const float4*>(kc + 2 * (e + 3));
                    #pragma unroll
                    for (int j = 0; j < 8; ++j) {
                        float bl = reinterpret_cast<float2&>(bd[j]).x;
                        float2& a0 = acc[(i + j + 2 * e)     % 40];
                        float2& a1 = acc[(i + j + 2 * e + 1) % 40];
                        a0.x = fmaf(cur.x, bl, a0.x);
                        a0.y = fmaf(cur.y, bl, a0.y);
                        a1.x = fmaf(cur.z, bl, a1.x);
                        a1.y = fmaf(cur.w, bl, a1.y);
                    }
                } else {
                    ulonglong2 cur = pkk;
                    const int en = ((e + 1) % 3 == 2) ? e + 2 : e + 1;
                    if (en < 16)
                        pkk = *reinterpret_cast<const ulonglong2*>(kc + 2 * en);
                    #pragma unroll
                    for (int j = 0; j < 8; ++j) {
                        PFMA(cur.x, bd[j], acc[(i + j + 2 * e)     % 40]);
                        PFMA(cur.y, bd[j], acc[(i + j + 2 * e + 1) % 40]);
                    }
                }
            }
            // dy = 32 tail tap, scalar
            {
                float2 k32 = *reinterpret_cast<const float2*>(kc + 32);
                #pragma unroll
                for (int j = 0; j < 8; ++j) {
                    float bl = reinterpret_cast<float2&>(bd[j]).x;
                    float2& a = acc[(i + j + 32) % 40];
                    a.x = fmaf(k32.x, bl, a.x);
                    a.y = fmaf(k32.y, bl, a.y);
                }
            }
            kc += 34;
        }
        // qy = s0+i .. s0+i+7 complete within this half: emit, recycle slots
        #pragma unroll
        for (int j = 0; j < 8; ++j) {
            float2 v = acc[(i + j) % 40];
            if (qx) { RED2(oemit, v.x, v.y); } else { RED1(oemit + 1, v.y); }
            acc[(i + j) % 40] = make_float2(0.f, 0.f);
            oemit += 2 * SENS;
        }
    }

    // drain slots for local qy = 16..47
    #pragma unroll
    for (int d = 16; d < 48; ++d) {
        if (ry == 1 && s0 + d == 63) { oemit += 2 * SENS; continue; }  // oy=127
        float2 v = acc[d % 40];
        if (qx) { RED2(oemit, v.x, v.y); } else { RED1(oemit + 1, v.y); }
        oemit += 2 * SENS;
    }
}

// ---------------- launch ----------------
extern "C" void kernel_launch(void* const* d_in, const int* in_sizes, int n_in,
                              void* d_out, int out_size) {
    const float* imgs = (const float*)d_in[0];
    const float* psf  = (const float*)d_in[1];
    const float* xc   = (const float*)d_in[4];
    const float* yc   = (const float*)d_in[5];
    float* out = (float*)d_out;

    (void)cudaFuncSetAttribute(conv_splat_kernel,
                               cudaFuncAttributeMaxDynamicSharedMemorySize, SMEM_BYTES);

    setup_kernel<<<ZERO_CTAS + BINPSF_CTAS, 256>>>(psf, (float4*)out);
    conv_splat_kernel<<<P_CNT * 2 * 8, 128, SMEM_BYTES>>>(imgs, xc, yc, out);
}

// round 12
// speedup vs baseline: 1.0420x; 1.0420x over previous
#include <cuda_runtime.h>
#include <cstdint>

typedef unsigned long long ull;

#define SENS   1024
#define P_CNT  256
#define KPSF   64

#define SROW   305                    // sBlk row stride (odd => conflict-free)
#define SK_ULL   (34 * 34)            // [u 34][dy 34pad] float2(k1[u-1], k0[u])
#define SB_FLT   (32 * SROW + 4)      // [s][ts 34 * 9 + n], ts=0/33 are zero pads
#define SMEM_BYTES (SK_ULL * 8 + SB_FLT * 4)

#define ZERO_CTAS   8192              // 8*1024*1024 floats / 4 / 256
#define BINPSF_TOT  (P_CNT * 2 * 34 * 34)
#define BINPSF_CTAS ((BINPSF_TOT + 255) / 256)

// Paired binned PSF: [p][ry][u 34][dy 34pad] -> float2(k_rx1[u-1], k_rx0[u])
__device__ float2 g_K[P_CNT * 2 * 34 * 34];

__device__ __forceinline__ ull ffma2(ull a, ull b, ull c) {
    ull d;
    asm("fma.rn.f32x2 %0, %1, %2, %3;" : "=l"(d) : "l"(a), "l"(b), "l"(c));
    return d;
}
__device__ __forceinline__ ull dup2(float v) {
    ull d;
    asm("mov.b64 %0, {%1, %1};" : "=l"(d) : "f"(v));
    return d;
}
#define RED2(ptr, a, b) \
    asm volatile("red.global.add.v2.f32 [%0], {%1, %2};" :: "l"(ptr), "f"(a), "f"(b) : "memory")
#define RED1(ptr, a) \
    asm volatile("red.global.add.f32 [%0], %1;" :: "l"(ptr), "f"(a) : "memory")

// ---------------- kernel 1: setup = zero sensor + bin PSF (merged) -----------
__global__ void setup_kernel(const float* __restrict__ psf,
                             float4* __restrict__ out) {
    const int bid = blockIdx.x;
    if (bid < ZERO_CTAS) {
        out[bid * 256 + threadIdx.x] = make_float4(0.f, 0.f, 0.f, 0.f);
        return;
    }
    int idx = (bid - ZERO_CTAS) * 256 + threadIdx.x;
    if (idx >= BINPSF_TOT) return;
    int dy = idx % 34;
    int u  = (idx / 34) % 34;
    int ry = (idx / (34 * 34)) & 1;
    int p  = idx / (34 * 34 * 2);
    float sx = 0.f, sy = 0.f;
    if (dy < 33) {
        const float* w = psf + (size_t)p * KPSF * KPSF;
        int r0  = 63 - ry - 2 * dy;
        int cx0 = 64 - 2 * u;       // rx=1, dx=u-1
        int cy0 = 63 - 2 * u;       // rx=0, dx=u
        #pragma unroll
        for (int a = 0; a < 2; ++a) {
            int rr = r0 + a;
            if (rr < 0 || rr > 63) continue;
            const float* row = w + rr * KPSF;
            #pragma unroll
            for (int c = 0; c < 2; ++c) {
                int ccx = cx0 + c;
                if (ccx >= 0 && ccx <= 63) sx += row[ccx];
                int ccy = cy0 + c;
                if (ccy >= 0 && ccy <= 63) sy += row[ccy];
            }
        }
    }
    g_K[idx] = make_float2(sx, sy);
}

// ---------------- kernel 2: conv, reuse-friendly FFMA2 ordering --------------
// FFMA2 with 3 distinct 64-bit operands is RF-bank limited to 1/3 cyc. Holding
// the SAME k operand across 8 consecutive FFMA2s lets the operand-reuse cache
// serve it (bank reads drop to {b, acc} = 2 even + 2 odd -> rt 2). So the
// inner loop is: [8x j with kk.x] then [8x reversed j with kk.y].
__global__ __launch_bounds__(128, 3)
void conv_splat_kernel(const float* __restrict__ imgs,
                       const float* __restrict__ xc,
                       const float* __restrict__ yc,
                       float* __restrict__ out)
{
    extern __shared__ ull dynsmem[];
    ull*   sK   = dynsmem;                                  // [34][34] float2
    float* sBlk = reinterpret_cast<float*>(dynsmem + SK_ULL); // [s][ts*9+n], stride 305

    const int bid  = blockIdx.x;
    // heavy-first octet ordering: groups of 512 CTAs, descending u-trip work
    const int grp  = bid >> 9;
    const int oct  = (0x70615243u >> (grp * 4)) & 7;   // {3,4,2,5,1,6,0,7}
    const int ry   = bid & 1;
    const int p    = (bid >> 1) & 255;
    const int tid  = threadIdx.x;
    const int lane = tid & 31;
    const int warp = tid >> 5;
    const int n    = lane & 7;
    const int xi   = (lane >> 3) & 1;
    const int sh   = lane >> 4;
    const int base = oct * 8 + warp * 2;
    const int qx   = base + xi;
    const int s0   = sh * 16;

    // load paired kernel (16B vectors)
    {
        const ulonglong2* kg = reinterpret_cast<const ulonglong2*>(
            reinterpret_cast<const ull*>(g_K) + (size_t)(p * 2 + ry) * SK_ULL);
        ulonglong2* sk2 = reinterpret_cast<ulonglong2*>(sK);
        for (int i = tid; i < SK_ULL / 2; i += 128) sk2[i] = kg[i];
    }
    // zero the two pad t-columns (ts = 0 and ts = 33)
    for (int i = tid; i < 32 * 2 * 8; i += 128) {
        int s  = i >> 4;
        int r  = i & 15;
        int ts = (r & 1) ? 33 : 0;
        int nn = r >> 1;
        sBlk[s * SROW + ts * 9 + nn] = 0.f;
    }
    // fill interior with float4 gmem loads (stride-9 scalar STS, conflict-free)
    const int bh = p & 15, bw = p >> 4;          // p = bw*16 + bh
    for (int i = tid; i < 32 * 8 * 8; i += 128) {
        int q  = i & 7;                           // float4 quad within row
        int nn = (i >> 3) & 7;
        int s  = i >> 6;
        float4 v = *reinterpret_cast<const float4*>(
            imgs + ((size_t)nn * 512 + bh * 32 + s) * 512 + bw * 32 + 4 * q);
        float* dst = &sBlk[s * SROW + (4 * q + 1) * 9 + nn];
        dst[0]      = v.x;
        dst[9]      = v.y;
        dst[18]     = v.z;
        dst[27]     = v.w;
    }
    __syncthreads();

    // splat geometry (all in-bounds for this problem's centers).
    const int ic = 512 + __float2int_rn(xc[p] * 1e6f);
    const int jc = 512 + __float2int_rn(yc[p] * 1e6f);
    float* oemit = out + (size_t)n * SENS * SENS
                 + (size_t)(ic - 63 + ry + 2 * s0) * SENS
                 + (jc - 64 + 2 * qx);

    // warp-uniform u range (union of useful taps over 2 qx)
    const int ulo = max(0, base - 31);
    const int uhi = min(33, base + 1);

    // per-thread b column base at (s = s0, ts = qx+1)
    const float* bcol0 = sBlk + s0 * SROW + (qx + 1) * 9 + n;

    ull acc[40];
    #pragma unroll
    for (int i = 0; i < 40; ++i) acc[i] = 0ULL;

    #pragma unroll
    for (int i = 0; i < 16; i += 8) {               // 8 local s-steps jointly
        const float* bp = bcol0 + i * SROW - ulo * 9;
        const ull*   kc = sK + ulo * 34;
        float braw[8];
        #pragma unroll
        for (int j = 0; j < 8; ++j) braw[j] = bp[j * SROW];
        for (int u = ulo; u <= uhi; ++u) {
            ull bd[8];
            #pragma unroll
            for (int j = 0; j < 8; ++j) bd[j] = dup2(braw[j]);
            bp -= 9;
            if (u < uhi) {
                #pragma unroll
                for (int j = 0; j < 8; ++j) braw[j] = bp[j * SROW];
            }
            // 2-stage pipelined kk stream; k component held constant across
            // 8 consecutive FFMA2s for operand-reuse (x group fwd, y group rev)
            ulonglong2 kk0 = *reinterpret_cast<const ulonglong2*>(kc);
            #pragma unroll
            for (int e = 0; e < 16; ++e) {
                ulonglong2 kk1;
                if (e < 15)
                    kk1 = *reinterpret_cast<const ulonglong2*>(kc + 2 * (e + 1));
                #pragma unroll
                for (int j = 0; j < 8; ++j)
                    acc[(i + j + 2 * e)     % 40] = ffma2(kk0.x, bd[j], acc[(i + j + 2 * e)     % 40]);
                #pragma unroll
                for (int j = 7; j >= 0; --j)
                    acc[(i + j + 2 * e + 1) % 40] = ffma2(kk0.y, bd[j], acc[(i + j + 2 * e + 1) % 40]);
                kk0 = kk1;
            }
            const ull k32 = kc[32];
            #pragma unroll
            for (int j = 0; j < 8; ++j)
                acc[(i + j + 32) % 40] = ffma2(k32, bd[j], acc[(i + j + 32) % 40]);
            kc += 34;
        }
        // qy = s0+i .. s0+i+7 complete within this half: emit, recycle slots
        #pragma unroll
        for (int j = 0; j < 8; ++j) {
            float2 v = *reinterpret_cast<float2*>(&acc[(i + j) % 40]);
            if (qx) { RED2(oemit, v.x, v.y); } else { RED1(oemit + 1, v.y); }
            acc[(i + j) % 40] = 0ULL;
            oemit += 2 * SENS;
        }
    }

    // drain slots for local qy = 16..47
    #pragma unroll
    for (int d = 16; d < 48; ++d) {
        if (ry == 1 && s0 + d == 63) { oemit += 2 * SENS; continue; }  // oy=127
        float2 v = *reinterpret_cast<float2*>(&acc[d % 40]);
        if (qx) { RED2(oemit, v.x, v.y); } else { RED1(oemit + 1, v.y); }
        oemit += 2 * SENS;
    }
}

// ---------------- launch ----------------
extern "C" void kernel_launch(void* const* d_in, const int* in_sizes, int n_in,
                              void* d_out, int out_size) {
    const float* imgs = (const float*)d_in[0];
    const float* psf  = (const float*)d_in[1];
    const float* xc   = (const float*)d_in[4];
    const float* yc   = (const float*)d_in[5];
    float* out = (float*)d_out;

    (void)cudaFuncSetAttribute(conv_splat_kernel,
                               cudaFuncAttributeMaxDynamicSharedMemorySize, SMEM_BYTES);

    setup_kernel<<<ZERO_CTAS + BINPSF_CTAS, 256>>>(psf, (float4*)out);
    conv_splat_kernel<<<P_CNT * 2 * 8, 128, SMEM_BYTES>>>(imgs, xc, yc, out);
}